// round 14
// baseline (speedup 1.0000x reference)
#include <cuda_runtime.h>
#include <cuda_fp16.h>
#include <cstdint>
#include <math.h>

#define BB   512
#define SS   200
#define DD   1024
#define PP   256
#define G4   4096
#define DIN  1280
#define NCTA 128
#define NTHR 512

#define WG_U32 17408   // gates weight slice per CTA in u32 (17*4*2*32*4)
#define WP_U32 16384   // proj weight slice per CTA in u32 (4*64*64)
#define ZC_F32 16384   // Zc tile (128 x 128)
#define RED_F32 (8 * 32 * 4)  // proj split-K reduction buffer (4KB)
#define SMEM_BYTES ((WG_U32 + WP_U32) * 4 + (ZC_F32 + RED_F32) * 4)

// ---------------- scratch (device globals; no allocation allowed) ----------------
__device__ float g_bias[G4];                       // folded bias
__device__ float g_Zc[(size_t)BB * G4];            // (512,4096) context+bias
__device__ float g_hs[(size_t)BB * SS * PP];       // all projected hiddens (heads)
__device__ unsigned int g_bar_count;               // grid barrier (cumulative)

// gates weights, fragment-packed fp16:
// u32 index = (((ct*17+it)*4+g)*2+jp)*32 + lane)*4 + reg
__device__ __align__(16) uint32_t g_Wpk[32 * 17 * 4 * 2 * 32 * 4];
// proj weights fp16: [((rt*4+wr)*64+kc)][lane 32][reg 2] u32
__device__ __align__(16) uint32_t g_Whrpk[8 * 4 * 64 * 64];
// pair-packed fp16 activations: h [m][kc16][q8], hraw [m][kc64][q8], x [t][m][q8]
__device__ __align__(16) uint32_t g_hpk[(size_t)BB * 16 * 8];
__device__ __align__(16) uint32_t g_hrawpk[(size_t)BB * 64 * 8];
__device__ __align__(16) uint32_t g_xpk[(size_t)SS * BB * 8];

// ---------------- helpers ----------------
__device__ __forceinline__ float sigf(float x) {
    float e = __expf(-x);
    return __fdividef(1.0f, 1.0f + e);
}
__device__ __forceinline__ float tanh_f(float x) {
    float e = __expf(-2.0f * fabsf(x));
    float t = __fdividef(1.0f - e, 1.0f + e);
    return copysignf(t, x);
}
__device__ __forceinline__ uint32_t pack_h2(float e0, float e1) {
    __half2 h = __floats2half2_rn(e0, e1);
    return *reinterpret_cast<uint32_t*>(&h);
}
__device__ __forceinline__ void mma_f16(float* d, const uint32_t* a, uint32_t b0, uint32_t b1) {
    asm volatile("mma.sync.aligned.m16n8k16.row.col.f32.f16.f16.f32 "
                 "{%0,%1,%2,%3}, {%4,%5,%6,%7}, {%8,%9}, {%0,%1,%2,%3};"
                 : "+f"(d[0]), "+f"(d[1]), "+f"(d[2]), "+f"(d[3])
                 : "r"(a[0]), "r"(a[1]), "r"(a[2]), "r"(a[3]), "r"(b0), "r"(b1));
}
// deterministic grid barrier: cumulative counter, target = bar_id * NCTA
__device__ __forceinline__ void grid_bar(unsigned int target) {
    __syncthreads();
    if (threadIdx.x == 0) {
        __threadfence();
        atomicAdd(&g_bar_count, 1u);
        while (atomicAdd(&g_bar_count, 0u) < target) { }
        __threadfence();
    }
    __syncthreads();
}

// ---------------- prologue 1: W_eff reduction -> fragment-packed (it=16), bias ----------------
__global__ __launch_bounds__(128) void prep_weff(
    const float* __restrict__ W_ih, const float* __restrict__ b_ih,
    const float* __restrict__ W_cmd, const float* __restrict__ b_cmd,
    const float* __restrict__ W_crd, const float* __restrict__ b_crd,
    const float* __restrict__ b_hh)
{
    int j = blockIdx.x;            // 0..4095 (gate-major row)
    int t = threadIdx.x;
    __shared__ float red[17][128];

    float acc[17];
#pragma unroll
    for (int c = 0; c < 17; c++) acc[c] = 0.0f;

    const float* wrow = W_ih + (size_t)j * DIN;
    for (int k = t; k < DD; k += 128) {
        float w = wrow[k];
#pragma unroll
        for (int c = 0; c < 10; c++) acc[c]      = fmaf(w, W_cmd[k * 10 + c], acc[c]);
#pragma unroll
        for (int c = 0; c < 6; c++)  acc[10 + c] = fmaf(w, W_crd[k * 6 + c], acc[10 + c]);
        acc[16] = fmaf(w, b_cmd[k] + b_crd[k], acc[16]);
    }
#pragma unroll
    for (int c = 0; c < 17; c++) red[c][t] = acc[c];
    __syncthreads();
    for (int off = 64; off > 0; off >>= 1) {
        if (t < off) {
#pragma unroll
            for (int c = 0; c < 17; c++) red[c][t] += red[c][t + off];
        }
        __syncthreads();
    }
    if (t == 0) {
        int g     = j >> 10;
        int jglob = j & 1023;
        int ct    = jglob >> 5;
        int rem   = jglob & 31;
        int nj    = rem >> 3;
        int l4    = rem & 7;
        int jp    = nj >> 1;
        int v     = nj & 1;
#pragma unroll
        for (int lq = 0; lq < 4; lq++) {
#pragma unroll
            for (int kh = 0; kh < 2; kh++) {
                size_t b4 = (size_t)((((ct * 17 + 16) * 4 + g) * 2 + jp) * 32 + (l4 * 4 + lq));
                size_t u = b4 * 4 + v * 2 + kh;
                g_Wpk[u] = pack_h2(red[2 * lq + 8 * kh][0], red[2 * lq + 8 * kh + 1][0]);
            }
        }
        g_bias[j] = red[16][0] + b_ih[j] + b_hh[j];
    }
}

// ---------------- prologue 2: Zc = ctx @ W_ih[:,1024:]^T + bias ----------------
__global__ __launch_bounds__(256) void prep_zc(
    const float* __restrict__ ctx, const float* __restrict__ W_ih)
{
    __shared__ float sA[64][17];
    __shared__ float sB[64][17];
    int n0 = blockIdx.x * 64;
    int m0 = blockIdx.y * 64;
    int tid = threadIdx.x;
    int tx = tid & 15;
    int ty = tid >> 4;

    float acc[4][4];
#pragma unroll
    for (int i = 0; i < 4; i++)
#pragma unroll
        for (int j = 0; j < 4; j++) acc[i][j] = 0.0f;

    for (int k0 = 0; k0 < 256; k0 += 16) {
        __syncthreads();
#pragma unroll
        for (int q = 0; q < 4; q++) {
            int e = q * 256 + tid;
            int r = e >> 4;
            int c = e & 15;
            sA[r][c] = ctx[(size_t)(m0 + r) * 256 + k0 + c];
            sB[r][c] = W_ih[(size_t)(n0 + r) * DIN + 1024 + k0 + c];
        }
        __syncthreads();
#pragma unroll
        for (int kk = 0; kk < 16; kk++) {
            float a[4];
            float b[4];
#pragma unroll
            for (int i = 0; i < 4; i++) a[i] = sA[ty + 16 * i][kk];
#pragma unroll
            for (int j = 0; j < 4; j++) b[j] = sB[tx + 16 * j][kk];
#pragma unroll
            for (int i = 0; i < 4; i++)
#pragma unroll
                for (int j = 0; j < 4; j++) acc[i][j] = fmaf(a[i], b[j], acc[i][j]);
        }
    }
#pragma unroll
    for (int i = 0; i < 4; i++) {
        int m = m0 + ty + 16 * i;
#pragma unroll
        for (int j = 0; j < 4; j++) {
            int n = n0 + tx + 16 * j;
            g_Zc[(size_t)m * G4 + n] = acc[i][j] + g_bias[n];
        }
    }
}

// ---------------- prologue 3 (merged): pack W_hh, W_hr, x; init barrier + h ----------------
// block ranges: [0,512) whh | [512,768) whr | [768,1168) x | [1168,1424) init
__global__ __launch_bounds__(256) void pack_all(
    const float* __restrict__ W_hh, const float* __restrict__ W_hr,
    const float* __restrict__ x)
{
    int b = blockIdx.x;
    if (b < 512) {
        int idx = b * 256 + threadIdx.x;        // 0..131071
        int lane = idx & 31;
        int jp   = (idx >> 5) & 1;
        int g    = (idx >> 6) & 3;
        int it   = (idx >> 8) & 15;
        int ct   = idx >> 12;                   // 0..31
        uint32_t h4[4];
#pragma unroll
        for (int v = 0; v < 2; v++) {
            int nj = 2 * jp + v;
#pragma unroll
            for (int kh = 0; kh < 2; kh++) {
                int n = (g << 10) + ct * 32 + nj * 8 + (lane >> 2);
                int k = it * 16 + 2 * (lane & 3) + 8 * kh;
                h4[v * 2 + kh] = pack_h2(W_hh[(size_t)n * 256 + k], W_hh[(size_t)n * 256 + k + 1]);
            }
        }
        size_t base = (size_t)((((ct * 17 + it) * 4 + g) * 2 + jp) * 32 + lane) * 4;
        *(uint4*)&g_Wpk[base] = make_uint4(h4[0], h4[1], h4[2], h4[3]);
    } else if (b < 768) {
        int idx = (b - 512) * 256 + threadIdx.x; // 0..65535
        int lane = idx & 31;
        int kc = (idx >> 5) & 63;
        int wr = (idx >> 11) & 3;
        int rt = idx >> 13;
        uint32_t h2[2];
#pragma unroll
        for (int bh = 0; bh < 2; bh++) {
            int n = rt * 32 + wr * 8 + (lane >> 2);
            int k = kc * 16 + 2 * (lane & 3) + 8 * bh;
            h2[bh] = pack_h2(W_hr[(size_t)n * 1024 + k], W_hr[(size_t)n * 1024 + k + 1]);
        }
        size_t base = (size_t)((rt * 4 + wr) * 64 + kc) * 64 + lane * 2;
        *(uint2*)&g_Whrpk[base] = make_uint2(h2[0], h2[1]);
    } else if (b < 1168) {
        int idx = (b - 768) * 256 + threadIdx.x; // 0..102399
        int m = idx & 511;
        int t = idx >> 9;
        const float* xr = x + ((size_t)m * SS + t) * 16;
        size_t base = ((size_t)t * 512 + m) * 8;
#pragma unroll
        for (int p = 0; p < 8; p++) {
            int q = (p < 4) ? 2 * p : 2 * (p - 4) + 1;
            g_xpk[base + q] = pack_h2(xr[2 * p], xr[2 * p + 1]);
        }
    } else {
        int i = (b - 1168) * 256 + threadIdx.x;  // 0..65535
        if (i == 0) g_bar_count = 0u;
        if (i < BB * 16 * 8) g_hpk[i] = 0u;
    }
}

// ---------------- persistent-kernel phase helpers ----------------
__device__ __forceinline__ void g_loadA(uint2 aH[2], int it, int t, int m0, int wm, int l4, int lq)
{
#pragma unroll
    for (int h = 0; h < 2; h++) {
        int row = m0 + wm * 16 + h * 8 + l4;
        if (it < 16) {
            size_t off = ((size_t)row * 16 + it) * 8 + lq * 2;
            aH[h] = __ldcg((const uint2*)(g_hpk + off));
        } else {
            size_t off = ((size_t)t * 512 + row) * 8 + lq * 2;
            aH[h] = __ldcg((const uint2*)(g_xpk + off));
        }
    }
}
__device__ __forceinline__ void p_loadA(uint2 aH[2], int kc, int mbase, int l4, int lq)
{
#pragma unroll
    for (int h = 0; h < 2; h++) {
        int row = mbase + h * 8 + l4;
        size_t off = ((size_t)row * 64 + kc) * 8 + lq * 2;
        aH[h] = __ldcg((const uint2*)&g_hrawpk[off]);
    }
}

// ---------------- persistent recurrence (512 threads = 16 warps) ----------------
// gates: warp (wm 0..7, jph 0..1): 16 m-rows x 64 cols (4 g x 1 jp), acc[4][2][4].
// proj:  warp (wm 0..1, wr 0..3, kh 0..1): split-K halves, smem reduce, kh=0 epilogue.
// smem: gates W (68KB) + proj W (64KB) + Zc (64KB) + red (4KB). c state in registers.
__global__ __launch_bounds__(NTHR, 1) void lstm_persistent()
{
    extern __shared__ uint32_t smemw[];
    uint32_t* sWg = smemw;                               // WG_U32
    uint32_t* sWp = smemw + WG_U32;                      // WP_U32
    float*    sZc = (float*)(smemw + WG_U32 + WP_U32);   // ZC_F32
    float*    sRed = sZc + ZC_F32;                       // RED_F32

    int bid = blockIdx.x;
    // gates tile map
    int ct = bid & 31;
    int mt = bid >> 5;
    int m0 = mt * 128;
    // proj tile map
    int rt2 = bid & 7;
    int mt2 = bid >> 3;

    int tid = threadIdx.x;
    int wid = tid >> 5;          // 0..15
    int lane = tid & 31;
    int l4 = lane >> 2;
    int lq = lane & 3;
    // gates warp coords
    int wm = wid >> 1;           // 0..7 (16 m-rows each)
    int jph = wid & 1;           // jp half
    // proj warp coords
    int pwm = wid >> 3;          // 0..1
    int pwr = (wid >> 1) & 3;    // 0..3
    int pkh = wid & 1;           // K half

    // ---- one-time staging: weight slices + Zc tile into smem ----
    {
        const uint4* srcg = (const uint4*)(g_Wpk + (size_t)ct * WG_U32);
        uint4* dstg = (uint4*)sWg;
        for (int i = tid; i < WG_U32 / 4; i += NTHR) dstg[i] = srcg[i];
        const uint4* srcp = (const uint4*)(g_Whrpk + (size_t)rt2 * WP_U32);
        uint4* dstp = (uint4*)sWp;
        for (int i = tid; i < WP_U32 / 4; i += NTHR) dstp[i] = srcp[i];
    }
    for (int idx = tid; idx < 128 * 128; idx += NTHR) {
        int ml = idx >> 7;
        int col = idx & 127;
        int g = col >> 5;
        int jl = col & 31;
        sZc[idx] = g_Zc[(size_t)(m0 + ml) * G4 + (g << 10) + ct * 32 + jl];
    }
    // cell state in registers: creg[h][v][pair] for this thread's fixed (m,j) coords
    float creg[2][2][2];
#pragma unroll
    for (int h = 0; h < 2; h++)
#pragma unroll
        for (int v = 0; v < 2; v++) {
            creg[h][v][0] = 0.0f;
            creg[h][v][1] = 0.0f;
        }
    __syncthreads();

    unsigned int bar = 0;

    for (int t = 0; t < SS; t++) {
        // ================= gates phase =================
        {
            float acc[4][2][4];
#pragma unroll
            for (int g = 0; g < 4; g++)
#pragma unroll
                for (int v = 0; v < 2; v++)
#pragma unroll
                    for (int q = 0; q < 4; q++) acc[g][v][q] = 0.0f;

            uint2 aH0[2], aH1[2];
            g_loadA(aH0, 0, t, m0, wm, l4, lq);
#pragma unroll
            for (int it = 0; it < 17; ++it) {
                if (it + 1 < 17) g_loadA(aH1, it + 1, t, m0, wm, l4, lq);
                uint32_t AH[4] = { aH0[0].x, aH0[1].x, aH0[0].y, aH0[1].y };
#pragma unroll
                for (int g = 0; g < 4; g++) {
                    uint4 h4 = *(const uint4*)&sWg[(((it * 4 + g) * 2 + jph) * 32 + lane) * 4];
                    mma_f16(acc[g][0], AH, h4.x, h4.y);
                    mma_f16(acc[g][1], AH, h4.z, h4.w);
                }
                aH0[0] = aH1[0];
                aH0[1] = aH1[1];
            }

            // epilogue: + Zc(smem), LSTM cell (c in regs), write pair-packed hraw
            int kc_w = ct * 2 + jph;
#pragma unroll
            for (int h = 0; h < 2; h++) {
                int ml = wm * 16 + h * 8 + l4;
                int m = m0 + ml;
                uint32_t pk[2];
#pragma unroll
                for (int v = 0; v < 2; v++) {
                    int jl = (2 * jph + v) * 8 + 2 * lq;
                    float pre0[4], pre1[4];
#pragma unroll
                    for (int g = 0; g < 4; g++) {
                        float2 zc = *(const float2*)&sZc[ml * 128 + g * 32 + jl];
                        pre0[g] = acc[g][v][2 * h + 0] + zc.x;
                        pre1[g] = acc[g][v][2 * h + 1] + zc.y;
                    }
                    float cn0 = sigf(pre0[1]) * creg[h][v][0] + sigf(pre0[0]) * tanh_f(pre0[2]);
                    float cn1 = sigf(pre1[1]) * creg[h][v][1] + sigf(pre1[0]) * tanh_f(pre1[2]);
                    creg[h][v][0] = cn0;
                    creg[h][v][1] = cn1;
                    float hr0 = sigf(pre0[3]) * tanh_f(cn0);
                    float hr1 = sigf(pre1[3]) * tanh_f(cn1);
                    pk[v] = pack_h2(hr0, hr1);
                }
                size_t hoff = ((size_t)m * 64 + kc_w) * 8 + 2 * lq;
                *(uint2*)&g_hrawpk[hoff] = make_uint2(pk[0], pk[1]);
            }
        }
        grid_bar(++bar * NCTA);

        // ================= projection phase (split-K over 16 warps) =================
        {
            int mbase = mt2 * 32 + pwm * 16;

            float acc[4] = {0.0f, 0.0f, 0.0f, 0.0f};
            uint2 aH0[2], aH1[2];
            int kc0 = pkh * 32;
            p_loadA(aH0, kc0, mbase, l4, lq);
#pragma unroll 8
            for (int kk = 0; kk < 32; ++kk) {
                int kc = kc0 + kk;
                if (kk + 1 < 32) p_loadA(aH1, kc + 1, mbase, l4, lq);
                uint32_t AH[4] = { aH0[0].x, aH0[1].x, aH0[0].y, aH0[1].y };
                uint2 bh = *(const uint2*)&sWp[(pwr * 64 + kc) * 64 + lane * 2];
                mma_f16(acc, AH, bh.x, bh.y);
                aH0[0] = aH1[0];
                aH0[1] = aH1[1];
            }

            int slot = ((pwm * 4 + pwr) * 32 + lane) * 4;
            if (pkh == 1) {
                *(float4*)&sRed[slot] = make_float4(acc[0], acc[1], acc[2], acc[3]);
            }
            __syncthreads();
            if (pkh == 0) {
                float4 o = *(const float4*)&sRed[slot];
                acc[0] += o.x;
                acc[1] += o.y;
                acc[2] += o.z;
                acc[3] += o.w;

                int r = rt2 * 32 + pwr * 8 + 2 * lq;
                int kc_h = rt2 * 2 + (pwr >> 1);
                int q = 2 * lq + (pwr & 1);
#pragma unroll
                for (int h = 0; h < 2; h++) {
                    int m = mbase + h * 8 + l4;
                    float v0 = acc[2 * h + 0];
                    float v1 = acc[2 * h + 1];
                    *(float2*)&g_hs[((size_t)m * SS + t) * PP + r] = make_float2(v0, v1);
                    g_hpk[((size_t)m * 16 + kc_h) * 8 + q] = pack_h2(v0, v1);
                }
            }
        }
        grid_bar(++bar * NCTA);
    }
}

// ---------------- output heads: LN + command logits + coords (warp per row) ----------------
__global__ __launch_bounds__(256) void head_kernel(
    const float* __restrict__ ln_g, const float* __restrict__ ln_b,
    const float* __restrict__ W_oc, const float* __restrict__ b_oc,
    const float* __restrict__ W_ox, const float* __restrict__ b_ox,
    const float* __restrict__ scale_p, float* __restrict__ out)
{
    int gw = (blockIdx.x * 256 + threadIdx.x) >> 5;
    int lane = threadIdx.x & 31;
    if (gw >= BB * SS) return;

    const float* hrow = g_hs + (size_t)gw * PP;
    float v[8];
#pragma unroll
    for (int q = 0; q < 2; q++) {
        float4 f = *reinterpret_cast<const float4*>(hrow + lane * 8 + q * 4);
        v[q * 4 + 0] = f.x;
        v[q * 4 + 1] = f.y;
        v[q * 4 + 2] = f.z;
        v[q * 4 + 3] = f.w;
    }
    float s = 0.0f;
    float s2 = 0.0f;
#pragma unroll
    for (int e = 0; e < 8; e++) {
        s += v[e];
        s2 = fmaf(v[e], v[e], s2);
    }
#pragma unroll
    for (int o = 16; o > 0; o >>= 1) {
        s  += __shfl_xor_sync(0xFFFFFFFFu, s, o);
        s2 += __shfl_xor_sync(0xFFFFFFFFu, s2, o);
    }
    float mean = s * (1.0f / 256.0f);
    float var = s2 * (1.0f / 256.0f) - mean * mean;
    float rstd = rsqrtf(var + 1e-5f);

    float hn[8];
#pragma unroll
    for (int e = 0; e < 8; e++) {
        int c = lane * 8 + e;
        hn[e] = (v[e] - mean) * rstd * ln_g[c] + ln_b[c];
    }

    float lgs[10];
#pragma unroll
    for (int cc = 0; cc < 10; cc++) {
        float p = 0.0f;
#pragma unroll
        for (int e = 0; e < 8; e++)
            p = fmaf(hn[e], W_oc[cc * 256 + lane * 8 + e], p);
#pragma unroll
        for (int o = 16; o > 0; o >>= 1) p += __shfl_xor_sync(0xFFFFFFFFu, p, o);
        p += b_oc[cc];
        lgs[cc] = p;
        if (lane == cc) out[(size_t)gw * 10 + cc] = p;
    }

    float csc = *scale_p;
    float* outc = out + (size_t)BB * SS * 10;
#pragma unroll
    for (int q = 0; q < 6; q++) {
        float p = 0.0f;
#pragma unroll
        for (int e = 0; e < 8; e++)
            p = fmaf(hn[e], W_ox[q * 266 + lane * 8 + e], p);
#pragma unroll
        for (int o = 16; o > 0; o >>= 1) p += __shfl_xor_sync(0xFFFFFFFFu, p, o);
#pragma unroll
        for (int cc = 0; cc < 10; cc++)
            p = fmaf(lgs[cc], W_ox[q * 266 + 256 + cc], p);
        p += b_ox[q];
        float z = tanh_f(p * csc);
        if (lane == q) outc[(size_t)gw * 6 + q] = z;
    }
}

// ---------------- launch ----------------
extern "C" void kernel_launch(void* const* d_in, const int* in_sizes, int n_in,
                              void* d_out, int out_size)
{
    const float* x      = (const float*)d_in[0];
    const float* ctx    = (const float*)d_in[1];
    const float* W_cmd  = (const float*)d_in[2];
    const float* b_cmd  = (const float*)d_in[3];
    const float* W_crd  = (const float*)d_in[4];
    const float* b_crd  = (const float*)d_in[5];
    const float* W_ih   = (const float*)d_in[6];
    const float* b_ih   = (const float*)d_in[7];
    const float* W_hh   = (const float*)d_in[8];
    const float* b_hh   = (const float*)d_in[9];
    const float* W_hr   = (const float*)d_in[10];
    const float* ln_g   = (const float*)d_in[11];
    const float* ln_b   = (const float*)d_in[12];
    const float* W_oc   = (const float*)d_in[13];
    const float* b_oc   = (const float*)d_in[14];
    const float* W_ox   = (const float*)d_in[15];
    const float* b_ox   = (const float*)d_in[16];
    const float* cscale = (const float*)d_in[17];
    float* out = (float*)d_out;

    static bool attr_set = false;
    if (!attr_set) {
        cudaFuncSetAttribute(lstm_persistent,
                             cudaFuncAttributeMaxDynamicSharedMemorySize,
                             SMEM_BYTES);
        attr_set = true;
    }

    prep_weff<<<G4, 128>>>(W_ih, b_ih, W_cmd, b_cmd, W_crd, b_crd, b_hh);
    prep_zc<<<dim3(G4 / 64, BB / 64), 256>>>(ctx, W_ih);
    pack_all<<<1424, 256>>>(W_hh, W_hr, x);

    lstm_persistent<<<NCTA, NTHR, SMEM_BYTES>>>();

    head_kernel<<<(BB * SS * 32 + 255) / 256, 256>>>(
        ln_g, ln_b, W_oc, b_oc, W_ox, b_ox, cscale, out);
}

// round 15
// speedup vs baseline: 1.0730x; 1.0730x over previous
#include <cuda_runtime.h>
#include <cuda_fp16.h>
#include <cstdint>
#include <math.h>

#define BB   512
#define SS   200
#define DD   1024
#define PP   256
#define G4   4096
#define DIN  1280
#define NCTA 128

#define WG_U32 17408   // gates weight slice per CTA in u32 (17*4*2*32*4)
#define WP_U32 16384   // proj weight slice per CTA in u32 (4*64*64)
#define ZC_F32 16384   // Zc tile (128 x 128)
#define SMEM_BYTES ((WG_U32 + WP_U32) * 4 + ZC_F32 * 4)

// ---------------- scratch (device globals; no allocation allowed) ----------------
__device__ float g_bias[G4];                       // folded bias
__device__ float g_Zc[(size_t)BB * G4];            // (512,4096) context+bias
__device__ float g_hs[(size_t)BB * SS * PP];       // all projected hiddens (heads)
__device__ unsigned int g_bar_count;               // grid barrier (cumulative)

// gates weights, fragment-packed fp16:
// u32 index = (((ct*17+it)*4+g)*2+jp)*32 + lane)*4 + reg
__device__ __align__(16) uint32_t g_Wpk[32 * 17 * 4 * 2 * 32 * 4];
// proj weights fp16: [((rt*4+wr)*64+kc)][lane 32][reg 2] u32
__device__ __align__(16) uint32_t g_Whrpk[8 * 4 * 64 * 64];
// pair-packed fp16 activations: h [m][kc16][q8], hraw [m][kc64][q8], x [t][m][q8]
__device__ __align__(16) uint32_t g_hpk[(size_t)BB * 16 * 8];
__device__ __align__(16) uint32_t g_hrawpk[(size_t)BB * 64 * 8];
__device__ __align__(16) uint32_t g_xpk[(size_t)SS * BB * 8];

// ---------------- helpers ----------------
// HW tanh (sm_75+): 1 MUFU instruction, max rel err ~2^-10.7 — comparable to the
// fp16 quantization (2^-11) already applied to hraw/h on the same pathway.
__device__ __forceinline__ float tanh_apx(float x) {
    float r;
    asm("tanh.approx.f32 %0, %1;" : "=f"(r) : "f"(x));
    return r;
}
__device__ __forceinline__ float sigf(float x) {
    return fmaf(tanh_apx(0.5f * x), 0.5f, 0.5f);
}
__device__ __forceinline__ float tanh_f(float x) { return tanh_apx(x); }
// exact tanh for the output head (errors there hit coord_out directly)
__device__ __forceinline__ float tanh_exact(float x) {
    float e = __expf(-2.0f * fabsf(x));
    float t = __fdividef(1.0f - e, 1.0f + e);
    return copysignf(t, x);
}
__device__ __forceinline__ uint32_t pack_h2(float e0, float e1) {
    __half2 h = __floats2half2_rn(e0, e1);
    return *reinterpret_cast<uint32_t*>(&h);
}
__device__ __forceinline__ void mma_f16(float* d, const uint32_t* a, uint32_t b0, uint32_t b1) {
    asm volatile("mma.sync.aligned.m16n8k16.row.col.f32.f16.f16.f32 "
                 "{%0,%1,%2,%3}, {%4,%5,%6,%7}, {%8,%9}, {%0,%1,%2,%3};"
                 : "+f"(d[0]), "+f"(d[1]), "+f"(d[2]), "+f"(d[3])
                 : "r"(a[0]), "r"(a[1]), "r"(a[2]), "r"(a[3]), "r"(b0), "r"(b1));
}
// deterministic grid barrier: cumulative counter, target = bar_id * NCTA
__device__ __forceinline__ void grid_bar(unsigned int target) {
    __syncthreads();
    if (threadIdx.x == 0) {
        __threadfence();
        atomicAdd(&g_bar_count, 1u);
        while (atomicAdd(&g_bar_count, 0u) < target) { }
        __threadfence();
    }
    __syncthreads();
}

// ---------------- prologue 1: W_eff reduction -> fragment-packed (it=16), bias ----------------
__global__ __launch_bounds__(128) void prep_weff(
    const float* __restrict__ W_ih, const float* __restrict__ b_ih,
    const float* __restrict__ W_cmd, const float* __restrict__ b_cmd,
    const float* __restrict__ W_crd, const float* __restrict__ b_crd,
    const float* __restrict__ b_hh)
{
    int j = blockIdx.x;            // 0..4095 (gate-major row)
    int t = threadIdx.x;
    __shared__ float red[17][128];

    float acc[17];
#pragma unroll
    for (int c = 0; c < 17; c++) acc[c] = 0.0f;

    const float* wrow = W_ih + (size_t)j * DIN;
    for (int k = t; k < DD; k += 128) {
        float w = wrow[k];
#pragma unroll
        for (int c = 0; c < 10; c++) acc[c]      = fmaf(w, W_cmd[k * 10 + c], acc[c]);
#pragma unroll
        for (int c = 0; c < 6; c++)  acc[10 + c] = fmaf(w, W_crd[k * 6 + c], acc[10 + c]);
        acc[16] = fmaf(w, b_cmd[k] + b_crd[k], acc[16]);
    }
#pragma unroll
    for (int c = 0; c < 17; c++) red[c][t] = acc[c];
    __syncthreads();
    for (int off = 64; off > 0; off >>= 1) {
        if (t < off) {
#pragma unroll
            for (int c = 0; c < 17; c++) red[c][t] += red[c][t + off];
        }
        __syncthreads();
    }
    if (t == 0) {
        int g     = j >> 10;
        int jglob = j & 1023;
        int ct    = jglob >> 5;
        int rem   = jglob & 31;
        int nj    = rem >> 3;
        int l4    = rem & 7;
        int jp    = nj >> 1;
        int v     = nj & 1;
#pragma unroll
        for (int lq = 0; lq < 4; lq++) {
#pragma unroll
            for (int kh = 0; kh < 2; kh++) {
                size_t b4 = (size_t)((((ct * 17 + 16) * 4 + g) * 2 + jp) * 32 + (l4 * 4 + lq));
                size_t u = b4 * 4 + v * 2 + kh;
                g_Wpk[u] = pack_h2(red[2 * lq + 8 * kh][0], red[2 * lq + 8 * kh + 1][0]);
            }
        }
        g_bias[j] = red[16][0] + b_ih[j] + b_hh[j];
    }
}

// ---------------- prologue 2: Zc = ctx @ W_ih[:,1024:]^T + bias ----------------
__global__ __launch_bounds__(256) void prep_zc(
    const float* __restrict__ ctx, const float* __restrict__ W_ih)
{
    __shared__ float sA[64][17];
    __shared__ float sB[64][17];
    int n0 = blockIdx.x * 64;
    int m0 = blockIdx.y * 64;
    int tid = threadIdx.x;
    int tx = tid & 15;
    int ty = tid >> 4;

    float acc[4][4];
#pragma unroll
    for (int i = 0; i < 4; i++)
#pragma unroll
        for (int j = 0; j < 4; j++) acc[i][j] = 0.0f;

    for (int k0 = 0; k0 < 256; k0 += 16) {
        __syncthreads();
#pragma unroll
        for (int q = 0; q < 4; q++) {
            int e = q * 256 + tid;
            int r = e >> 4;
            int c = e & 15;
            sA[r][c] = ctx[(size_t)(m0 + r) * 256 + k0 + c];
            sB[r][c] = W_ih[(size_t)(n0 + r) * DIN + 1024 + k0 + c];
        }
        __syncthreads();
#pragma unroll
        for (int kk = 0; kk < 16; kk++) {
            float a[4];
            float b[4];
#pragma unroll
            for (int i = 0; i < 4; i++) a[i] = sA[ty + 16 * i][kk];
#pragma unroll
            for (int j = 0; j < 4; j++) b[j] = sB[tx + 16 * j][kk];
#pragma unroll
            for (int i = 0; i < 4; i++)
#pragma unroll
                for (int j = 0; j < 4; j++) acc[i][j] = fmaf(a[i], b[j], acc[i][j]);
        }
    }
#pragma unroll
    for (int i = 0; i < 4; i++) {
        int m = m0 + ty + 16 * i;
#pragma unroll
        for (int j = 0; j < 4; j++) {
            int n = n0 + tx + 16 * j;
            g_Zc[(size_t)m * G4 + n] = acc[i][j] + g_bias[n];
        }
    }
}

// ---------------- prologue 3 (merged): pack W_hh, W_hr, x; init barrier + h ----------------
// block ranges: [0,512) whh | [512,768) whr | [768,1168) x | [1168,1424) init
__global__ __launch_bounds__(256) void pack_all(
    const float* __restrict__ W_hh, const float* __restrict__ W_hr,
    const float* __restrict__ x)
{
    int b = blockIdx.x;
    if (b < 512) {
        int idx = b * 256 + threadIdx.x;        // 0..131071
        int lane = idx & 31;
        int jp   = (idx >> 5) & 1;
        int g    = (idx >> 6) & 3;
        int it   = (idx >> 8) & 15;
        int ct   = idx >> 12;                   // 0..31
        uint32_t h4[4];
#pragma unroll
        for (int v = 0; v < 2; v++) {
            int nj = 2 * jp + v;
#pragma unroll
            for (int kh = 0; kh < 2; kh++) {
                int n = (g << 10) + ct * 32 + nj * 8 + (lane >> 2);
                int k = it * 16 + 2 * (lane & 3) + 8 * kh;
                h4[v * 2 + kh] = pack_h2(W_hh[(size_t)n * 256 + k], W_hh[(size_t)n * 256 + k + 1]);
            }
        }
        size_t base = (size_t)((((ct * 17 + it) * 4 + g) * 2 + jp) * 32 + lane) * 4;
        *(uint4*)&g_Wpk[base] = make_uint4(h4[0], h4[1], h4[2], h4[3]);
    } else if (b < 768) {
        int idx = (b - 512) * 256 + threadIdx.x; // 0..65535
        int lane = idx & 31;
        int kc = (idx >> 5) & 63;
        int wr = (idx >> 11) & 3;
        int rt = idx >> 13;
        uint32_t h2[2];
#pragma unroll
        for (int bh = 0; bh < 2; bh++) {
            int n = rt * 32 + wr * 8 + (lane >> 2);
            int k = kc * 16 + 2 * (lane & 3) + 8 * bh;
            h2[bh] = pack_h2(W_hr[(size_t)n * 1024 + k], W_hr[(size_t)n * 1024 + k + 1]);
        }
        size_t base = (size_t)((rt * 4 + wr) * 64 + kc) * 64 + lane * 2;
        *(uint2*)&g_Whrpk[base] = make_uint2(h2[0], h2[1]);
    } else if (b < 1168) {
        int idx = (b - 768) * 256 + threadIdx.x; // 0..102399
        int m = idx & 511;
        int t = idx >> 9;
        const float* xr = x + ((size_t)m * SS + t) * 16;
        size_t base = ((size_t)t * 512 + m) * 8;
#pragma unroll
        for (int p = 0; p < 8; p++) {
            int q = (p < 4) ? 2 * p : 2 * (p - 4) + 1;
            g_xpk[base + q] = pack_h2(xr[2 * p], xr[2 * p + 1]);
        }
    } else {
        int i = (b - 1168) * 256 + threadIdx.x;  // 0..65535
        if (i == 0) g_bar_count = 0u;
        if (i < BB * 16 * 8) g_hpk[i] = 0u;
    }
}

// ---------------- persistent-kernel phase helpers ----------------
__device__ __forceinline__ void g_loadA(uint2 aH[2], int it, int t, int m0, int wid, int l4, int lq)
{
#pragma unroll
    for (int h = 0; h < 2; h++) {
        int row = m0 + wid * 16 + h * 8 + l4;
        if (it < 16) {
            size_t off = ((size_t)row * 16 + it) * 8 + lq * 2;
            aH[h] = __ldcg((const uint2*)(g_hpk + off));
        } else {
            size_t off = ((size_t)t * 512 + row) * 8 + lq * 2;
            aH[h] = __ldcg((const uint2*)(g_xpk + off));
        }
    }
}
__device__ __forceinline__ void p_loadA(uint2 aH[2], int kc, int mbase, int l4, int lq)
{
#pragma unroll
    for (int h = 0; h < 2; h++) {
        int row = mbase + h * 8 + l4;
        size_t off = ((size_t)row * 64 + kc) * 8 + lq * 2;
        aH[h] = __ldcg((const uint2*)&g_hrawpk[off]);
    }
}

// ---------------- persistent recurrence (256 threads, best-known config) ----------------
// gates map: 4 m-tiles (128 rows) x 32 col-tiles (32 j x 4 gates).
// smem: gates W slice (68KB) + proj W slice (64KB) + Zc tile (64KB). c state in registers.
__global__ __launch_bounds__(256, 1) void lstm_persistent()
{
    extern __shared__ uint32_t smemw[];
    uint32_t* sWg = smemw;                         // WG_U32
    uint32_t* sWp = smemw + WG_U32;                // WP_U32
    float*    sZc = (float*)(smemw + WG_U32 + WP_U32); // ZC_F32

    int bid = blockIdx.x;
    // gates tile map
    int ct = bid & 31;
    int mt = bid >> 5;
    int m0 = mt * 128;
    // proj tile map
    int rt2 = bid & 7;
    int mt2 = bid >> 3;

    int tid = threadIdx.x;
    int wid = tid >> 5;
    int lane = tid & 31;
    int l4 = lane >> 2;
    int lq = lane & 3;

    // ---- one-time staging: weight slices + Zc tile into smem ----
    {
        const uint4* srcg = (const uint4*)(g_Wpk + (size_t)ct * WG_U32);
        uint4* dstg = (uint4*)sWg;
        for (int i = tid; i < WG_U32 / 4; i += 256) dstg[i] = srcg[i];
        const uint4* srcp = (const uint4*)(g_Whrpk + (size_t)rt2 * WP_U32);
        uint4* dstp = (uint4*)sWp;
        for (int i = tid; i < WP_U32 / 4; i += 256) dstp[i] = srcp[i];
    }
    for (int idx = tid; idx < 128 * 128; idx += 256) {
        int ml = idx >> 7;
        int col = idx & 127;
        int g = col >> 5;
        int jl = col & 31;
        sZc[idx] = g_Zc[(size_t)(m0 + ml) * G4 + (g << 10) + ct * 32 + jl];
    }
    // cell state in registers: creg[h][nj][0/1] for this thread's fixed (m,j) coords
    float creg[2][4][2];
#pragma unroll
    for (int h = 0; h < 2; h++)
#pragma unroll
        for (int nj = 0; nj < 4; nj++) {
            creg[h][nj][0] = 0.0f;
            creg[h][nj][1] = 0.0f;
        }
    __syncthreads();

    unsigned int bar = 0;

    for (int t = 0; t < SS; t++) {
        // ================= gates phase =================
        {
            float acc[4][4][4];
#pragma unroll
            for (int g = 0; g < 4; g++)
#pragma unroll
                for (int nj = 0; nj < 4; nj++)
#pragma unroll
                    for (int q = 0; q < 4; q++) acc[g][nj][q] = 0.0f;

            uint2 aH0[2], aH1[2];
            g_loadA(aH0, 0, t, m0, wid, l4, lq);
#pragma unroll
            for (int it = 0; it < 17; ++it) {
                if (it + 1 < 17) g_loadA(aH1, it + 1, t, m0, wid, l4, lq);
                uint32_t AH[4] = { aH0[0].x, aH0[1].x, aH0[0].y, aH0[1].y };
#pragma unroll
                for (int g = 0; g < 4; g++) {
#pragma unroll
                    for (int jp = 0; jp < 2; jp++) {
                        uint4 h4 = *(const uint4*)&sWg[((((it * 4 + g) * 2 + jp) * 32 + lane)) * 4];
                        mma_f16(acc[g][2 * jp + 0], AH, h4.x, h4.y);
                        mma_f16(acc[g][2 * jp + 1], AH, h4.z, h4.w);
                    }
                }
                aH0[0] = aH1[0];
                aH0[1] = aH1[1];
            }

            // epilogue: + Zc(smem), LSTM cell (c in regs), write pair-packed hraw
#pragma unroll
            for (int h = 0; h < 2; h++) {
                int ml = wid * 16 + h * 8 + l4;
                int m = m0 + ml;
#pragma unroll
                for (int nj = 0; nj < 4; nj++) {
                    int jl = nj * 8 + 2 * lq;
                    float pre0[4], pre1[4];
#pragma unroll
                    for (int g = 0; g < 4; g++) {
                        float2 zc = *(const float2*)&sZc[ml * 128 + g * 32 + jl];
                        pre0[g] = acc[g][nj][2 * h + 0] + zc.x;
                        pre1[g] = acc[g][nj][2 * h + 1] + zc.y;
                    }
                    float cn0 = sigf(pre0[1]) * creg[h][nj][0] + sigf(pre0[0]) * tanh_f(pre0[2]);
                    float cn1 = sigf(pre1[1]) * creg[h][nj][1] + sigf(pre1[0]) * tanh_f(pre1[2]);
                    creg[h][nj][0] = cn0;
                    creg[h][nj][1] = cn1;
                    float hr0 = sigf(pre0[3]) * tanh_f(cn0);
                    float hr1 = sigf(pre1[3]) * tanh_f(cn1);
                    int q = 2 * lq + (nj & 1);
                    int kc = ct * 2 + (nj >> 1);
                    g_hrawpk[((size_t)m * 64 + kc) * 8 + q] = pack_h2(hr0, hr1);
                }
            }
        }
        grid_bar(++bar * NCTA);

        // ================= projection phase =================
        {
            int wm = wid >> 2;
            int wr = wid & 3;
            int mbase = mt2 * 32 + wm * 16;

            float acc[4] = {0.0f, 0.0f, 0.0f, 0.0f};
            uint2 aH0[2], aH1[2];
            p_loadA(aH0, 0, mbase, l4, lq);
#pragma unroll 8
            for (int kc = 0; kc < 64; ++kc) {
                if (kc + 1 < 64) p_loadA(aH1, kc + 1, mbase, l4, lq);
                uint32_t AH[4] = { aH0[0].x, aH0[1].x, aH0[0].y, aH0[1].y };
                uint2 bh = *(const uint2*)&sWp[(wr * 64 + kc) * 64 + lane * 2];
                mma_f16(acc, AH, bh.x, bh.y);
                aH0[0] = aH1[0];
                aH0[1] = aH1[1];
            }

            int r = rt2 * 32 + wr * 8 + 2 * lq;
            int kc_h = rt2 * 2 + (wr >> 1);
            int q = 2 * lq + (wr & 1);
#pragma unroll
            for (int h = 0; h < 2; h++) {
                int m = mbase + h * 8 + l4;
                float v0 = acc[2 * h + 0];
                float v1 = acc[2 * h + 1];
                *(float2*)&g_hs[((size_t)m * SS + t) * PP + r] = make_float2(v0, v1);
                g_hpk[((size_t)m * 16 + kc_h) * 8 + q] = pack_h2(v0, v1);
            }
        }
        grid_bar(++bar * NCTA);
    }
}

// ---------------- output heads: LN + command logits + coords (warp per row) ----------------
__global__ __launch_bounds__(256) void head_kernel(
    const float* __restrict__ ln_g, const float* __restrict__ ln_b,
    const float* __restrict__ W_oc, const float* __restrict__ b_oc,
    const float* __restrict__ W_ox, const float* __restrict__ b_ox,
    const float* __restrict__ scale_p, float* __restrict__ out)
{
    int gw = (blockIdx.x * 256 + threadIdx.x) >> 5;
    int lane = threadIdx.x & 31;
    if (gw >= BB * SS) return;

    const float* hrow = g_hs + (size_t)gw * PP;
    float v[8];
#pragma unroll
    for (int q = 0; q < 2; q++) {
        float4 f = *reinterpret_cast<const float4*>(hrow + lane * 8 + q * 4);
        v[q * 4 + 0] = f.x;
        v[q * 4 + 1] = f.y;
        v[q * 4 + 2] = f.z;
        v[q * 4 + 3] = f.w;
    }
    float s = 0.0f;
    float s2 = 0.0f;
#pragma unroll
    for (int e = 0; e < 8; e++) {
        s += v[e];
        s2 = fmaf(v[e], v[e], s2);
    }
#pragma unroll
    for (int o = 16; o > 0; o >>= 1) {
        s  += __shfl_xor_sync(0xFFFFFFFFu, s, o);
        s2 += __shfl_xor_sync(0xFFFFFFFFu, s2, o);
    }
    float mean = s * (1.0f / 256.0f);
    float var = s2 * (1.0f / 256.0f) - mean * mean;
    float rstd = rsqrtf(var + 1e-5f);

    float hn[8];
#pragma unroll
    for (int e = 0; e < 8; e++) {
        int c = lane * 8 + e;
        hn[e] = (v[e] - mean) * rstd * ln_g[c] + ln_b[c];
    }

    float lgs[10];
#pragma unroll
    for (int cc = 0; cc < 10; cc++) {
        float p = 0.0f;
#pragma unroll
        for (int e = 0; e < 8; e++)
            p = fmaf(hn[e], W_oc[cc * 256 + lane * 8 + e], p);
#pragma unroll
        for (int o = 16; o > 0; o >>= 1) p += __shfl_xor_sync(0xFFFFFFFFu, p, o);
        p += b_oc[cc];
        lgs[cc] = p;
        if (lane == cc) out[(size_t)gw * 10 + cc] = p;
    }

    float csc = *scale_p;
    float* outc = out + (size_t)BB * SS * 10;
#pragma unroll
    for (int q = 0; q < 6; q++) {
        float p = 0.0f;
#pragma unroll
        for (int e = 0; e < 8; e++)
            p = fmaf(hn[e], W_ox[q * 266 + lane * 8 + e], p);
#pragma unroll
        for (int o = 16; o > 0; o >>= 1) p += __shfl_xor_sync(0xFFFFFFFFu, p, o);
#pragma unroll
        for (int cc = 0; cc < 10; cc++)
            p = fmaf(lgs[cc], W_ox[q * 266 + 256 + cc], p);
        p += b_ox[q];
        float z = tanh_exact(p * csc);
        if (lane == q) outc[(size_t)gw * 6 + q] = z;
    }
}

// ---------------- launch ----------------
extern "C" void kernel_launch(void* const* d_in, const int* in_sizes, int n_in,
                              void* d_out, int out_size)
{
    const float* x      = (const float*)d_in[0];
    const float* ctx    = (const float*)d_in[1];
    const float* W_cmd  = (const float*)d_in[2];
    const float* b_cmd  = (const float*)d_in[3];
    const float* W_crd  = (const float*)d_in[4];
    const float* b_crd  = (const float*)d_in[5];
    const float* W_ih   = (const float*)d_in[6];
    const float* b_ih   = (const float*)d_in[7];
    const float* W_hh   = (const float*)d_in[8];
    const float* b_hh   = (const float*)d_in[9];
    const float* W_hr   = (const float*)d_in[10];
    const float* ln_g   = (const float*)d_in[11];
    const float* ln_b   = (const float*)d_in[12];
    const float* W_oc   = (const float*)d_in[13];
    const float* b_oc   = (const float*)d_in[14];
    const float* W_ox   = (const float*)d_in[15];
    const float* b_ox   = (const float*)d_in[16];
    const float* cscale = (const float*)d_in[17];
    float* out = (float*)d_out;

    static bool attr_set = false;
    if (!attr_set) {
        cudaFuncSetAttribute(lstm_persistent,
                             cudaFuncAttributeMaxDynamicSharedMemorySize,
                             SMEM_BYTES);
        attr_set = true;
    }

    prep_weff<<<G4, 128>>>(W_ih, b_ih, W_cmd, b_cmd, W_crd, b_crd, b_hh);
    prep_zc<<<dim3(G4 / 64, BB / 64), 256>>>(ctx, W_ih);
    pack_all<<<1424, 256>>>(W_hh, W_hr, x);

    lstm_persistent<<<NCTA, 256, SMEM_BYTES>>>();

    head_kernel<<<(BB * SS * 32 + 255) / 256, 256>>>(
        ln_g, ln_b, W_oc, b_oc, W_ox, b_ox, cscale, out);
}

// round 16
// speedup vs baseline: 1.4326x; 1.3352x over previous
#include <cuda_runtime.h>
#include <cuda_fp16.h>
#include <cstdint>
#include <math.h>

#define BB   512
#define SS   200
#define DD   1024
#define PP   256
#define G4   4096
#define DIN  1280
#define NCTA 128

#define WG_U32 17408   // gates weight slice per CTA in u32 (17*4*2*32*4)
#define WP_U32 16384   // proj weight slice per CTA in u32 (4*64*64)
#define ZC_F32 16384   // Zc tile (128 x 128)
#define RED_F32 (2 * 3 * 4 * 32 * 4)  // proj split-K partials (12KB)
#define SMEM_BYTES ((WG_U32 + WP_U32) * 4 + (ZC_F32 + RED_F32) * 4)

// ---------------- scratch (device globals; no allocation allowed) ----------------
__device__ float g_bias[G4];                       // folded bias
__device__ float g_Zc[(size_t)BB * G4];            // (512,4096) context+bias
__device__ float g_hs[(size_t)BB * SS * PP];       // all projected hiddens (heads)
__device__ unsigned int g_bar_count;               // grid barrier (cumulative)

// gates weights, fragment-packed fp16:
// u32 index = (((ct*17+it)*4+g)*2+jp)*32 + lane)*4 + reg
__device__ __align__(16) uint32_t g_Wpk[32 * 17 * 4 * 2 * 32 * 4];
// proj weights fp16: [((rt*4+rs)*64+kc)][lane 32][reg 2] u32
__device__ __align__(16) uint32_t g_Whrpk[8 * 4 * 64 * 64];
// pair-packed fp16 activations: h [m][kc16][q8], hraw [m][kc64][q8], x [t][m][q8]
__device__ __align__(16) uint32_t g_hpk[(size_t)BB * 16 * 8];
__device__ __align__(16) uint32_t g_hrawpk[(size_t)BB * 64 * 8];
__device__ __align__(16) uint32_t g_xpk[(size_t)SS * BB * 8];

// ---------------- helpers ----------------
__device__ __forceinline__ float tanh_apx(float x) {
    float r;
    asm("tanh.approx.f32 %0, %1;" : "=f"(r) : "f"(x));
    return r;
}
__device__ __forceinline__ float sigf(float x) {
    return fmaf(tanh_apx(0.5f * x), 0.5f, 0.5f);
}
__device__ __forceinline__ float tanh_f(float x) { return tanh_apx(x); }
// exact tanh for the output head (errors there hit coord_out directly)
__device__ __forceinline__ float tanh_exact(float x) {
    float e = __expf(-2.0f * fabsf(x));
    float t = __fdividef(1.0f - e, 1.0f + e);
    return copysignf(t, x);
}
__device__ __forceinline__ uint32_t pack_h2(float e0, float e1) {
    __half2 h = __floats2half2_rn(e0, e1);
    return *reinterpret_cast<uint32_t*>(&h);
}
__device__ __forceinline__ void mma_f16(float* d, const uint32_t* a, uint32_t b0, uint32_t b1) {
    asm volatile("mma.sync.aligned.m16n8k16.row.col.f32.f16.f16.f32 "
                 "{%0,%1,%2,%3}, {%4,%5,%6,%7}, {%8,%9}, {%0,%1,%2,%3};"
                 : "+f"(d[0]), "+f"(d[1]), "+f"(d[2]), "+f"(d[3])
                 : "r"(a[0]), "r"(a[1]), "r"(a[2]), "r"(a[3]), "r"(b0), "r"(b1));
}
// deterministic grid barrier: cumulative counter, target = bar_id * NCTA
__device__ __forceinline__ void grid_bar(unsigned int target) {
    __syncthreads();
    if (threadIdx.x == 0) {
        __threadfence();
        atomicAdd(&g_bar_count, 1u);
        while (atomicAdd(&g_bar_count, 0u) < target) { }
        __threadfence();
    }
    __syncthreads();
}

// ---------------- prologue 1: W_eff reduction -> fragment-packed (it=16), bias ----------------
__global__ __launch_bounds__(128) void prep_weff(
    const float* __restrict__ W_ih, const float* __restrict__ b_ih,
    const float* __restrict__ W_cmd, const float* __restrict__ b_cmd,
    const float* __restrict__ W_crd, const float* __restrict__ b_crd,
    const float* __restrict__ b_hh)
{
    int j = blockIdx.x;            // 0..4095 (gate-major row)
    int t = threadIdx.x;
    __shared__ float red[17][128];

    float acc[17];
#pragma unroll
    for (int c = 0; c < 17; c++) acc[c] = 0.0f;

    const float* wrow = W_ih + (size_t)j * DIN;
    for (int k = t; k < DD; k += 128) {
        float w = wrow[k];
#pragma unroll
        for (int c = 0; c < 10; c++) acc[c]      = fmaf(w, W_cmd[k * 10 + c], acc[c]);
#pragma unroll
        for (int c = 0; c < 6; c++)  acc[10 + c] = fmaf(w, W_crd[k * 6 + c], acc[10 + c]);
        acc[16] = fmaf(w, b_cmd[k] + b_crd[k], acc[16]);
    }
#pragma unroll
    for (int c = 0; c < 17; c++) red[c][t] = acc[c];
    __syncthreads();
    for (int off = 64; off > 0; off >>= 1) {
        if (t < off) {
#pragma unroll
            for (int c = 0; c < 17; c++) red[c][t] += red[c][t + off];
        }
        __syncthreads();
    }
    if (t == 0) {
        int g     = j >> 10;
        int jglob = j & 1023;
        int ct    = jglob >> 5;
        int rem   = jglob & 31;
        int nj    = rem >> 3;
        int l4    = rem & 7;
        int jp    = nj >> 1;
        int v     = nj & 1;
#pragma unroll
        for (int lq = 0; lq < 4; lq++) {
#pragma unroll
            for (int kh = 0; kh < 2; kh++) {
                size_t b4 = (size_t)((((ct * 17 + 16) * 4 + g) * 2 + jp) * 32 + (l4 * 4 + lq));
                size_t u = b4 * 4 + v * 2 + kh;
                g_Wpk[u] = pack_h2(red[2 * lq + 8 * kh][0], red[2 * lq + 8 * kh + 1][0]);
            }
        }
        g_bias[j] = red[16][0] + b_ih[j] + b_hh[j];
    }
}

// ---------------- prologue 2: Zc = ctx @ W_ih[:,1024:]^T + bias ----------------
__global__ __launch_bounds__(256) void prep_zc(
    const float* __restrict__ ctx, const float* __restrict__ W_ih)
{
    __shared__ float sA[64][17];
    __shared__ float sB[64][17];
    int n0 = blockIdx.x * 64;
    int m0 = blockIdx.y * 64;
    int tid = threadIdx.x;
    int tx = tid & 15;
    int ty = tid >> 4;

    float acc[4][4];
#pragma unroll
    for (int i = 0; i < 4; i++)
#pragma unroll
        for (int j = 0; j < 4; j++) acc[i][j] = 0.0f;

    for (int k0 = 0; k0 < 256; k0 += 16) {
        __syncthreads();
#pragma unroll
        for (int q = 0; q < 4; q++) {
            int e = q * 256 + tid;
            int r = e >> 4;
            int c = e & 15;
            sA[r][c] = ctx[(size_t)(m0 + r) * 256 + k0 + c];
            sB[r][c] = W_ih[(size_t)(n0 + r) * DIN + 1024 + k0 + c];
        }
        __syncthreads();
#pragma unroll
        for (int kk = 0; kk < 16; kk++) {
            float a[4];
            float b[4];
#pragma unroll
            for (int i = 0; i < 4; i++) a[i] = sA[ty + 16 * i][kk];
#pragma unroll
            for (int j = 0; j < 4; j++) b[j] = sB[tx + 16 * j][kk];
#pragma unroll
            for (int i = 0; i < 4; i++)
#pragma unroll
                for (int j = 0; j < 4; j++) acc[i][j] = fmaf(a[i], b[j], acc[i][j]);
        }
    }
#pragma unroll
    for (int i = 0; i < 4; i++) {
        int m = m0 + ty + 16 * i;
#pragma unroll
        for (int j = 0; j < 4; j++) {
            int n = n0 + tx + 16 * j;
            g_Zc[(size_t)m * G4 + n] = acc[i][j] + g_bias[n];
        }
    }
}

// ---------------- prologue 3 (merged): pack W_hh, W_hr, x; init barrier + h ----------------
// block ranges: [0,512) whh | [512,768) whr | [768,1168) x | [1168,1424) init
__global__ __launch_bounds__(256) void pack_all(
    const float* __restrict__ W_hh, const float* __restrict__ W_hr,
    const float* __restrict__ x)
{
    int b = blockIdx.x;
    if (b < 512) {
        int idx = b * 256 + threadIdx.x;        // 0..131071
        int lane = idx & 31;
        int jp   = (idx >> 5) & 1;
        int g    = (idx >> 6) & 3;
        int it   = (idx >> 8) & 15;
        int ct   = idx >> 12;                   // 0..31
        uint32_t h4[4];
#pragma unroll
        for (int v = 0; v < 2; v++) {
            int nj = 2 * jp + v;
#pragma unroll
            for (int kh = 0; kh < 2; kh++) {
                int n = (g << 10) + ct * 32 + nj * 8 + (lane >> 2);
                int k = it * 16 + 2 * (lane & 3) + 8 * kh;
                h4[v * 2 + kh] = pack_h2(W_hh[(size_t)n * 256 + k], W_hh[(size_t)n * 256 + k + 1]);
            }
        }
        size_t base = (size_t)((((ct * 17 + it) * 4 + g) * 2 + jp) * 32 + lane) * 4;
        *(uint4*)&g_Wpk[base] = make_uint4(h4[0], h4[1], h4[2], h4[3]);
    } else if (b < 768) {
        int idx = (b - 512) * 256 + threadIdx.x; // 0..65535
        int lane = idx & 31;
        int kc = (idx >> 5) & 63;
        int rs = (idx >> 11) & 3;
        int rt = idx >> 13;
        uint32_t h2[2];
#pragma unroll
        for (int bh = 0; bh < 2; bh++) {
            int n = rt * 32 + rs * 8 + (lane >> 2);
            int k = kc * 16 + 2 * (lane & 3) + 8 * bh;
            h2[bh] = pack_h2(W_hr[(size_t)n * 1024 + k], W_hr[(size_t)n * 1024 + k + 1]);
        }
        size_t base = (size_t)((rt * 4 + rs) * 64 + kc) * 64 + lane * 2;
        *(uint2*)&g_Whrpk[base] = make_uint2(h2[0], h2[1]);
    } else if (b < 1168) {
        int idx = (b - 768) * 256 + threadIdx.x; // 0..102399
        int m = idx & 511;
        int t = idx >> 9;
        const float* xr = x + ((size_t)m * SS + t) * 16;
        size_t base = ((size_t)t * 512 + m) * 8;
#pragma unroll
        for (int p = 0; p < 8; p++) {
            int q = (p < 4) ? 2 * p : 2 * (p - 4) + 1;
            g_xpk[base + q] = pack_h2(xr[2 * p], xr[2 * p + 1]);
        }
    } else {
        int i = (b - 1168) * 256 + threadIdx.x;  // 0..65535
        if (i == 0) g_bar_count = 0u;
        if (i < BB * 16 * 8) g_hpk[i] = 0u;
    }
}

// ---------------- persistent-kernel phase helpers ----------------
__device__ __forceinline__ void g_loadA(uint2 aH[2], int it, int t, int m0, int wid, int l4, int lq)
{
#pragma unroll
    for (int h = 0; h < 2; h++) {
        int row = m0 + wid * 16 + h * 8 + l4;
        if (it < 16) {
            size_t off = ((size_t)row * 16 + it) * 8 + lq * 2;
            aH[h] = __ldcg((const uint2*)(g_hpk + off));
        } else {
            size_t off = ((size_t)t * 512 + row) * 8 + lq * 2;
            aH[h] = __ldcg((const uint2*)(g_xpk + off));
        }
    }
}

// ---------------- persistent recurrence (256 threads) ----------------
// gates map: 4 m-tiles (128 rows) x 32 col-tiles (32 j x 4 gates).
// proj: 4-way split-K, warp (wm, kq): 16 m-rows, 16 kc, all 32 r; A batched in regs.
// smem: gates W (68KB) + proj W (64KB) + Zc (64KB) + red (12KB). c state in registers.
__global__ __launch_bounds__(256, 1) void lstm_persistent()
{
    extern __shared__ uint32_t smemw[];
    uint32_t* sWg = smemw;                               // WG_U32
    uint32_t* sWp = smemw + WG_U32;                      // WP_U32
    float*    sZc = (float*)(smemw + WG_U32 + WP_U32);   // ZC_F32
    float*    sRed = sZc + ZC_F32;                       // RED_F32

    int bid = blockIdx.x;
    // gates tile map
    int ct = bid & 31;
    int mt = bid >> 5;
    int m0 = mt * 128;
    // proj tile map
    int rt2 = bid & 7;
    int mt2 = bid >> 3;

    int tid = threadIdx.x;
    int wid = tid >> 5;
    int lane = tid & 31;
    int l4 = lane >> 2;
    int lq = lane & 3;

    // ---- one-time staging: weight slices + Zc tile into smem ----
    {
        const uint4* srcg = (const uint4*)(g_Wpk + (size_t)ct * WG_U32);
        uint4* dstg = (uint4*)sWg;
        for (int i = tid; i < WG_U32 / 4; i += 256) dstg[i] = srcg[i];
        const uint4* srcp = (const uint4*)(g_Whrpk + (size_t)rt2 * WP_U32);
        uint4* dstp = (uint4*)sWp;
        for (int i = tid; i < WP_U32 / 4; i += 256) dstp[i] = srcp[i];
    }
    for (int idx = tid; idx < 128 * 128; idx += 256) {
        int ml = idx >> 7;
        int col = idx & 127;
        int g = col >> 5;
        int jl = col & 31;
        sZc[idx] = g_Zc[(size_t)(m0 + ml) * G4 + (g << 10) + ct * 32 + jl];
    }
    // cell state in registers: creg[h][nj][0/1] for this thread's fixed (m,j) coords
    float creg[2][4][2];
#pragma unroll
    for (int h = 0; h < 2; h++)
#pragma unroll
        for (int nj = 0; nj < 4; nj++) {
            creg[h][nj][0] = 0.0f;
            creg[h][nj][1] = 0.0f;
        }
    __syncthreads();

    unsigned int bar = 0;

    for (int t = 0; t < SS; t++) {
        // ================= gates phase =================
        {
            float acc[4][4][4];
#pragma unroll
            for (int g = 0; g < 4; g++)
#pragma unroll
                for (int nj = 0; nj < 4; nj++)
#pragma unroll
                    for (int q = 0; q < 4; q++) acc[g][nj][q] = 0.0f;

            uint2 aH0[2], aH1[2];
            g_loadA(aH0, 0, t, m0, wid, l4, lq);
#pragma unroll
            for (int it = 0; it < 17; ++it) {
                if (it + 1 < 17) g_loadA(aH1, it + 1, t, m0, wid, l4, lq);
                uint32_t AH[4] = { aH0[0].x, aH0[1].x, aH0[0].y, aH0[1].y };
#pragma unroll
                for (int g = 0; g < 4; g++) {
#pragma unroll
                    for (int jp = 0; jp < 2; jp++) {
                        uint4 h4 = *(const uint4*)&sWg[((((it * 4 + g) * 2 + jp) * 32 + lane)) * 4];
                        mma_f16(acc[g][2 * jp + 0], AH, h4.x, h4.y);
                        mma_f16(acc[g][2 * jp + 1], AH, h4.z, h4.w);
                    }
                }
                aH0[0] = aH1[0];
                aH0[1] = aH1[1];
            }

            // epilogue: + Zc(smem), LSTM cell (c in regs), write pair-packed hraw
#pragma unroll
            for (int h = 0; h < 2; h++) {
                int ml = wid * 16 + h * 8 + l4;
                int m = m0 + ml;
#pragma unroll
                for (int nj = 0; nj < 4; nj++) {
                    int jl = nj * 8 + 2 * lq;
                    float pre0[4], pre1[4];
#pragma unroll
                    for (int g = 0; g < 4; g++) {
                        float2 zc = *(const float2*)&sZc[ml * 128 + g * 32 + jl];
                        pre0[g] = acc[g][nj][2 * h + 0] + zc.x;
                        pre1[g] = acc[g][nj][2 * h + 1] + zc.y;
                    }
                    float cn0 = sigf(pre0[1]) * creg[h][nj][0] + sigf(pre0[0]) * tanh_f(pre0[2]);
                    float cn1 = sigf(pre1[1]) * creg[h][nj][1] + sigf(pre1[0]) * tanh_f(pre1[2]);
                    creg[h][nj][0] = cn0;
                    creg[h][nj][1] = cn1;
                    float hr0 = sigf(pre0[3]) * tanh_f(cn0);
                    float hr1 = sigf(pre1[3]) * tanh_f(cn1);
                    int q = 2 * lq + (nj & 1);
                    int kc = ct * 2 + (nj >> 1);
                    g_hrawpk[((size_t)m * 64 + kc) * 8 + q] = pack_h2(hr0, hr1);
                }
            }
        }
        grid_bar(++bar * NCTA);

        // ================= projection phase (4-way split-K, batched A) =================
        {
            int wm = wid >> 2;          // 0..1  (16 m-rows each)
            int kq = wid & 3;           // 0..3  (16 kc each)
            int mbase = mt2 * 32 + wm * 16;

            // batched A: all 32 LDG.64 issued up-front (MLP=32, one latency)
            uint2 aA[16][2];
#pragma unroll
            for (int kk = 0; kk < 16; kk++) {
                int kc = kq * 16 + kk;
#pragma unroll
                for (int h = 0; h < 2; h++) {
                    int row = mbase + h * 8 + l4;
                    aA[kk][h] = __ldcg((const uint2*)&g_hrawpk[((size_t)row * 64 + kc) * 8 + lq * 2]);
                }
            }

            float acc[4][4];
#pragma unroll
            for (int rs = 0; rs < 4; rs++)
#pragma unroll
                for (int q = 0; q < 4; q++) acc[rs][q] = 0.0f;

#pragma unroll
            for (int kk = 0; kk < 16; kk++) {
                int kc = kq * 16 + kk;
                uint32_t AH[4] = { aA[kk][0].x, aA[kk][1].x, aA[kk][0].y, aA[kk][1].y };
#pragma unroll
                for (int rs = 0; rs < 4; rs++) {
                    uint2 bh = *(const uint2*)&sWp[(rs * 64 + kc) * 64 + lane * 2];
                    mma_f16(acc[rs], AH, bh.x, bh.y);
                }
            }

            if (kq != 0) {
#pragma unroll
                for (int rs = 0; rs < 4; rs++) {
                    int slot = (((wm * 3 + (kq - 1)) * 4 + rs) * 32 + lane) * 4;
                    *(float4*)&sRed[slot] = make_float4(acc[rs][0], acc[rs][1], acc[rs][2], acc[rs][3]);
                }
            }
            __syncthreads();
            if (kq == 0) {
#pragma unroll
                for (int rs = 0; rs < 4; rs++) {
#pragma unroll
                    for (int p = 0; p < 3; p++) {
                        int slot = (((wm * 3 + p) * 4 + rs) * 32 + lane) * 4;
                        float4 o = *(const float4*)&sRed[slot];
                        acc[rs][0] += o.x;
                        acc[rs][1] += o.y;
                        acc[rs][2] += o.z;
                        acc[rs][3] += o.w;
                    }
                    int r = rt2 * 32 + rs * 8 + 2 * lq;
                    int kc_h = rt2 * 2 + (rs >> 1);
                    int q = 2 * lq + (rs & 1);
#pragma unroll
                    for (int h = 0; h < 2; h++) {
                        int m = mbase + h * 8 + l4;
                        float v0 = acc[rs][2 * h + 0];
                        float v1 = acc[rs][2 * h + 1];
                        *(float2*)&g_hs[((size_t)m * SS + t) * PP + r] = make_float2(v0, v1);
                        g_hpk[((size_t)m * 16 + kc_h) * 8 + q] = pack_h2(v0, v1);
                    }
                }
            }
        }
        grid_bar(++bar * NCTA);
    }
}

// ---------------- output heads: LN + command logits + coords (warp per row) ----------------
__global__ __launch_bounds__(256) void head_kernel(
    const float* __restrict__ ln_g, const float* __restrict__ ln_b,
    const float* __restrict__ W_oc, const float* __restrict__ b_oc,
    const float* __restrict__ W_ox, const float* __restrict__ b_ox,
    const float* __restrict__ scale_p, float* __restrict__ out)
{
    int gw = (blockIdx.x * 256 + threadIdx.x) >> 5;
    int lane = threadIdx.x & 31;
    if (gw >= BB * SS) return;

    const float* hrow = g_hs + (size_t)gw * PP;
    float v[8];
#pragma unroll
    for (int q = 0; q < 2; q++) {
        float4 f = *reinterpret_cast<const float4*>(hrow + lane * 8 + q * 4);
        v[q * 4 + 0] = f.x;
        v[q * 4 + 1] = f.y;
        v[q * 4 + 2] = f.z;
        v[q * 4 + 3] = f.w;
    }
    float s = 0.0f;
    float s2 = 0.0f;
#pragma unroll
    for (int e = 0; e < 8; e++) {
        s += v[e];
        s2 = fmaf(v[e], v[e], s2);
    }
#pragma unroll
    for (int o = 16; o > 0; o >>= 1) {
        s  += __shfl_xor_sync(0xFFFFFFFFu, s, o);
        s2 += __shfl_xor_sync(0xFFFFFFFFu, s2, o);
    }
    float mean = s * (1.0f / 256.0f);
    float var = s2 * (1.0f / 256.0f) - mean * mean;
    float rstd = rsqrtf(var + 1e-5f);

    float hn[8];
#pragma unroll
    for (int e = 0; e < 8; e++) {
        int c = lane * 8 + e;
        hn[e] = (v[e] - mean) * rstd * ln_g[c] + ln_b[c];
    }

    float lgs[10];
#pragma unroll
    for (int cc = 0; cc < 10; cc++) {
        float p = 0.0f;
#pragma unroll
        for (int e = 0; e < 8; e++)
            p = fmaf(hn[e], W_oc[cc * 256 + lane * 8 + e], p);
#pragma unroll
        for (int o = 16; o > 0; o >>= 1) p += __shfl_xor_sync(0xFFFFFFFFu, p, o);
        p += b_oc[cc];
        lgs[cc] = p;
        if (lane == cc) out[(size_t)gw * 10 + cc] = p;
    }

    float csc = *scale_p;
    float* outc = out + (size_t)BB * SS * 10;
#pragma unroll
    for (int q = 0; q < 6; q++) {
        float p = 0.0f;
#pragma unroll
        for (int e = 0; e < 8; e++)
            p = fmaf(hn[e], W_ox[q * 266 + lane * 8 + e], p);
#pragma unroll
        for (int o = 16; o > 0; o >>= 1) p += __shfl_xor_sync(0xFFFFFFFFu, p, o);
#pragma unroll
        for (int cc = 0; cc < 10; cc++)
            p = fmaf(lgs[cc], W_ox[q * 266 + 256 + cc], p);
        p += b_ox[q];
        float z = tanh_exact(p * csc);
        if (lane == q) outc[(size_t)gw * 6 + q] = z;
    }
}

// ---------------- launch ----------------
extern "C" void kernel_launch(void* const* d_in, const int* in_sizes, int n_in,
                              void* d_out, int out_size)
{
    const float* x      = (const float*)d_in[0];
    const float* ctx    = (const float*)d_in[1];
    const float* W_cmd  = (const float*)d_in[2];
    const float* b_cmd  = (const float*)d_in[3];
    const float* W_crd  = (const float*)d_in[4];
    const float* b_crd  = (const float*)d_in[5];
    const float* W_ih   = (const float*)d_in[6];
    const float* b_ih   = (const float*)d_in[7];
    const float* W_hh   = (const float*)d_in[8];
    const float* b_hh   = (const float*)d_in[9];
    const float* W_hr   = (const float*)d_in[10];
    const float* ln_g   = (const float*)d_in[11];
    const float* ln_b   = (const float*)d_in[12];
    const float* W_oc   = (const float*)d_in[13];
    const float* b_oc   = (const float*)d_in[14];
    const float* W_ox   = (const float*)d_in[15];
    const float* b_ox   = (const float*)d_in[16];
    const float* cscale = (const float*)d_in[17];
    float* out = (float*)d_out;

    static bool attr_set = false;
    if (!attr_set) {
        cudaFuncSetAttribute(lstm_persistent,
                             cudaFuncAttributeMaxDynamicSharedMemorySize,
                             SMEM_BYTES);
        attr_set = true;
    }

    prep_weff<<<G4, 128>>>(W_ih, b_ih, W_cmd, b_cmd, W_crd, b_crd, b_hh);
    prep_zc<<<dim3(G4 / 64, BB / 64), 256>>>(ctx, W_ih);
    pack_all<<<1424, 256>>>(W_hh, W_hr, x);

    lstm_persistent<<<NCTA, 256, SMEM_BYTES>>>();

    head_kernel<<<(BB * SS * 32 + 255) / 256, 256>>>(
        ln_g, ln_b, W_oc, b_oc, W_ox, b_ox, cscale, out);
}

// round 17
// speedup vs baseline: 1.4371x; 1.0032x over previous
#include <cuda_runtime.h>
#include <cuda_fp16.h>
#include <cstdint>
#include <math.h>

#define BB   512
#define SS   200
#define DD   1024
#define PP   256
#define G4   4096
#define DIN  1280
#define NCTA 128

#define WG_U32 17408   // gates weight slice per CTA in u32 (17*4*2*32*4)
#define WP_U32 16384   // proj weight slice per CTA in u32 (4*64*64)
#define ZC_F32 16384   // Zc tile (128 x 128)
#define RED_F32 (2 * 3 * 4 * 32 * 4)  // proj split-K partials (12KB)
#define SMEM_BYTES ((WG_U32 + WP_U32) * 4 + (ZC_F32 + RED_F32) * 4)

// ---------------- scratch (device globals; no allocation allowed) ----------------
__device__ float g_bias[G4];                       // folded bias
__device__ float g_Zc[(size_t)BB * G4];            // (512,4096) context+bias
__device__ float g_hs[(size_t)BB * SS * PP];       // all projected hiddens (heads)
__device__ unsigned int g_bar_count;               // grid barrier (cumulative)

// gates weights, fragment-packed fp16:
// u32 index = (((ct*17+it)*4+g)*2+jp)*32 + lane)*4 + reg
__device__ __align__(16) uint32_t g_Wpk[32 * 17 * 4 * 2 * 32 * 4];
// proj weights fp16: [((rt*4+rs)*64+kc)][lane 32][reg 2] u32
__device__ __align__(16) uint32_t g_Whrpk[8 * 4 * 64 * 64];
// pair-packed fp16 activations: h [m][kc16][q8], hraw [m][kc64][q8], x [t][m][q8]
__device__ __align__(16) uint32_t g_hpk[(size_t)BB * 16 * 8];
__device__ __align__(16) uint32_t g_hrawpk[(size_t)BB * 64 * 8];
__device__ __align__(16) uint32_t g_xpk[(size_t)SS * BB * 8];

// ---------------- helpers ----------------
__device__ __forceinline__ float tanh_apx(float x) {
    float r;
    asm("tanh.approx.f32 %0, %1;" : "=f"(r) : "f"(x));
    return r;
}
__device__ __forceinline__ float sigf(float x) {
    return fmaf(tanh_apx(0.5f * x), 0.5f, 0.5f);
}
__device__ __forceinline__ float tanh_f(float x) { return tanh_apx(x); }
// exact tanh for the output head (errors there hit coord_out directly)
__device__ __forceinline__ float tanh_exact(float x) {
    float e = __expf(-2.0f * fabsf(x));
    float t = __fdividef(1.0f - e, 1.0f + e);
    return copysignf(t, x);
}
__device__ __forceinline__ uint32_t pack_h2(float e0, float e1) {
    __half2 h = __floats2half2_rn(e0, e1);
    return *reinterpret_cast<uint32_t*>(&h);
}
__device__ __forceinline__ void mma_f16(float* d, const uint32_t* a, uint32_t b0, uint32_t b1) {
    asm volatile("mma.sync.aligned.m16n8k16.row.col.f32.f16.f16.f32 "
                 "{%0,%1,%2,%3}, {%4,%5,%6,%7}, {%8,%9}, {%0,%1,%2,%3};"
                 : "+f"(d[0]), "+f"(d[1]), "+f"(d[2]), "+f"(d[3])
                 : "r"(a[0]), "r"(a[1]), "r"(a[2]), "r"(a[3]), "r"(b0), "r"(b1));
}
// deterministic grid barrier: cumulative counter, target = bar_id * NCTA
__device__ __forceinline__ void grid_bar(unsigned int target) {
    __syncthreads();
    if (threadIdx.x == 0) {
        __threadfence();
        atomicAdd(&g_bar_count, 1u);
        while (atomicAdd(&g_bar_count, 0u) < target) { }
        __threadfence();
    }
    __syncthreads();
}

// ---------------- prologue 1: W_eff reduction -> fragment-packed (it=16), bias ----------------
__global__ __launch_bounds__(128) void prep_weff(
    const float* __restrict__ W_ih, const float* __restrict__ b_ih,
    const float* __restrict__ W_cmd, const float* __restrict__ b_cmd,
    const float* __restrict__ W_crd, const float* __restrict__ b_crd,
    const float* __restrict__ b_hh)
{
    int j = blockIdx.x;            // 0..4095 (gate-major row)
    int t = threadIdx.x;
    __shared__ float red[17][128];

    float acc[17];
#pragma unroll
    for (int c = 0; c < 17; c++) acc[c] = 0.0f;

    const float* wrow = W_ih + (size_t)j * DIN;
    for (int k = t; k < DD; k += 128) {
        float w = wrow[k];
#pragma unroll
        for (int c = 0; c < 10; c++) acc[c]      = fmaf(w, W_cmd[k * 10 + c], acc[c]);
#pragma unroll
        for (int c = 0; c < 6; c++)  acc[10 + c] = fmaf(w, W_crd[k * 6 + c], acc[10 + c]);
        acc[16] = fmaf(w, b_cmd[k] + b_crd[k], acc[16]);
    }
#pragma unroll
    for (int c = 0; c < 17; c++) red[c][t] = acc[c];
    __syncthreads();
    for (int off = 64; off > 0; off >>= 1) {
        if (t < off) {
#pragma unroll
            for (int c = 0; c < 17; c++) red[c][t] += red[c][t + off];
        }
        __syncthreads();
    }
    if (t == 0) {
        int g     = j >> 10;
        int jglob = j & 1023;
        int ct    = jglob >> 5;
        int rem   = jglob & 31;
        int nj    = rem >> 3;
        int l4    = rem & 7;
        int jp    = nj >> 1;
        int v     = nj & 1;
#pragma unroll
        for (int lq = 0; lq < 4; lq++) {
#pragma unroll
            for (int kh = 0; kh < 2; kh++) {
                size_t b4 = (size_t)((((ct * 17 + 16) * 4 + g) * 2 + jp) * 32 + (l4 * 4 + lq));
                size_t u = b4 * 4 + v * 2 + kh;
                g_Wpk[u] = pack_h2(red[2 * lq + 8 * kh][0], red[2 * lq + 8 * kh + 1][0]);
            }
        }
        g_bias[j] = red[16][0] + b_ih[j] + b_hh[j];
    }
}

// ---------------- prologue 2: Zc = ctx @ W_ih[:,1024:]^T + bias ----------------
__global__ __launch_bounds__(256) void prep_zc(
    const float* __restrict__ ctx, const float* __restrict__ W_ih)
{
    __shared__ float sA[64][17];
    __shared__ float sB[64][17];
    int n0 = blockIdx.x * 64;
    int m0 = blockIdx.y * 64;
    int tid = threadIdx.x;
    int tx = tid & 15;
    int ty = tid >> 4;

    float acc[4][4];
#pragma unroll
    for (int i = 0; i < 4; i++)
#pragma unroll
        for (int j = 0; j < 4; j++) acc[i][j] = 0.0f;

    for (int k0 = 0; k0 < 256; k0 += 16) {
        __syncthreads();
#pragma unroll
        for (int q = 0; q < 4; q++) {
            int e = q * 256 + tid;
            int r = e >> 4;
            int c = e & 15;
            sA[r][c] = ctx[(size_t)(m0 + r) * 256 + k0 + c];
            sB[r][c] = W_ih[(size_t)(n0 + r) * DIN + 1024 + k0 + c];
        }
        __syncthreads();
#pragma unroll
        for (int kk = 0; kk < 16; kk++) {
            float a[4];
            float b[4];
#pragma unroll
            for (int i = 0; i < 4; i++) a[i] = sA[ty + 16 * i][kk];
#pragma unroll
            for (int j = 0; j < 4; j++) b[j] = sB[tx + 16 * j][kk];
#pragma unroll
            for (int i = 0; i < 4; i++)
#pragma unroll
                for (int j = 0; j < 4; j++) acc[i][j] = fmaf(a[i], b[j], acc[i][j]);
        }
    }
#pragma unroll
    for (int i = 0; i < 4; i++) {
        int m = m0 + ty + 16 * i;
#pragma unroll
        for (int j = 0; j < 4; j++) {
            int n = n0 + tx + 16 * j;
            g_Zc[(size_t)m * G4 + n] = acc[i][j] + g_bias[n];
        }
    }
}

// ---------------- prologue 3 (merged): pack W_hh, W_hr, x; init barrier + h ----------------
// block ranges: [0,512) whh | [512,768) whr | [768,1168) x | [1168,1424) init
__global__ __launch_bounds__(256) void pack_all(
    const float* __restrict__ W_hh, const float* __restrict__ W_hr,
    const float* __restrict__ x)
{
    int b = blockIdx.x;
    if (b < 512) {
        int idx = b * 256 + threadIdx.x;        // 0..131071
        int lane = idx & 31;
        int jp   = (idx >> 5) & 1;
        int g    = (idx >> 6) & 3;
        int it   = (idx >> 8) & 15;
        int ct   = idx >> 12;                   // 0..31
        uint32_t h4[4];
#pragma unroll
        for (int v = 0; v < 2; v++) {
            int nj = 2 * jp + v;
#pragma unroll
            for (int kh = 0; kh < 2; kh++) {
                int n = (g << 10) + ct * 32 + nj * 8 + (lane >> 2);
                int k = it * 16 + 2 * (lane & 3) + 8 * kh;
                h4[v * 2 + kh] = pack_h2(W_hh[(size_t)n * 256 + k], W_hh[(size_t)n * 256 + k + 1]);
            }
        }
        size_t base = (size_t)((((ct * 17 + it) * 4 + g) * 2 + jp) * 32 + lane) * 4;
        *(uint4*)&g_Wpk[base] = make_uint4(h4[0], h4[1], h4[2], h4[3]);
    } else if (b < 768) {
        int idx = (b - 512) * 256 + threadIdx.x; // 0..65535
        int lane = idx & 31;
        int kc = (idx >> 5) & 63;
        int rs = (idx >> 11) & 3;
        int rt = idx >> 13;
        uint32_t h2[2];
#pragma unroll
        for (int bh = 0; bh < 2; bh++) {
            int n = rt * 32 + rs * 8 + (lane >> 2);
            int k = kc * 16 + 2 * (lane & 3) + 8 * bh;
            h2[bh] = pack_h2(W_hr[(size_t)n * 1024 + k], W_hr[(size_t)n * 1024 + k + 1]);
        }
        size_t base = (size_t)((rt * 4 + rs) * 64 + kc) * 64 + lane * 2;
        *(uint2*)&g_Whrpk[base] = make_uint2(h2[0], h2[1]);
    } else if (b < 1168) {
        int idx = (b - 768) * 256 + threadIdx.x; // 0..102399
        int m = idx & 511;
        int t = idx >> 9;
        const float* xr = x + ((size_t)m * SS + t) * 16;
        size_t base = ((size_t)t * 512 + m) * 8;
#pragma unroll
        for (int p = 0; p < 8; p++) {
            int q = (p < 4) ? 2 * p : 2 * (p - 4) + 1;
            g_xpk[base + q] = pack_h2(xr[2 * p], xr[2 * p + 1]);
        }
    } else {
        int i = (b - 1168) * 256 + threadIdx.x;  // 0..65535
        if (i == 0) g_bar_count = 0u;
        if (i < BB * 16 * 8) g_hpk[i] = 0u;
    }
}

// ---------------- persistent recurrence (256 threads) ----------------
// gates: batched A (all 17 iterations' operands loaded up-front, MLP=34).
// proj: 4-way split-K, warp (wm, kq): 16 m-rows, 16 kc, all 32 r; A batched in regs.
// smem: gates W (68KB) + proj W (64KB) + Zc (64KB) + red (12KB). c state in registers.
__global__ __launch_bounds__(256, 1) void lstm_persistent()
{
    extern __shared__ uint32_t smemw[];
    uint32_t* sWg = smemw;                               // WG_U32
    uint32_t* sWp = smemw + WG_U32;                      // WP_U32
    float*    sZc = (float*)(smemw + WG_U32 + WP_U32);   // ZC_F32
    float*    sRed = sZc + ZC_F32;                       // RED_F32

    int bid = blockIdx.x;
    // gates tile map
    int ct = bid & 31;
    int mt = bid >> 5;
    int m0 = mt * 128;
    // proj tile map
    int rt2 = bid & 7;
    int mt2 = bid >> 3;

    int tid = threadIdx.x;
    int wid = tid >> 5;
    int lane = tid & 31;
    int l4 = lane >> 2;
    int lq = lane & 3;

    // ---- one-time staging: weight slices + Zc tile into smem ----
    {
        const uint4* srcg = (const uint4*)(g_Wpk + (size_t)ct * WG_U32);
        uint4* dstg = (uint4*)sWg;
        for (int i = tid; i < WG_U32 / 4; i += 256) dstg[i] = srcg[i];
        const uint4* srcp = (const uint4*)(g_Whrpk + (size_t)rt2 * WP_U32);
        uint4* dstp = (uint4*)sWp;
        for (int i = tid; i < WP_U32 / 4; i += 256) dstp[i] = srcp[i];
    }
    for (int idx = tid; idx < 128 * 128; idx += 256) {
        int ml = idx >> 7;
        int col = idx & 127;
        int g = col >> 5;
        int jl = col & 31;
        sZc[idx] = g_Zc[(size_t)(m0 + ml) * G4 + (g << 10) + ct * 32 + jl];
    }
    // cell state in registers: creg[h][nj][0/1] for this thread's fixed (m,j) coords
    float creg[2][4][2];
#pragma unroll
    for (int h = 0; h < 2; h++)
#pragma unroll
        for (int nj = 0; nj < 4; nj++) {
            creg[h][nj][0] = 0.0f;
            creg[h][nj][1] = 0.0f;
        }
    __syncthreads();

    unsigned int bar = 0;

    for (int t = 0; t < SS; t++) {
        // ================= gates phase (batched A: all 17 iterations up-front) =================
        {
            // issue all 34 LDG.64 first: one L2 latency covers everything
            uint2 aA[17][2];
#pragma unroll
            for (int it = 0; it < 17; ++it) {
#pragma unroll
                for (int h = 0; h < 2; h++) {
                    int row = m0 + wid * 16 + h * 8 + l4;
                    if (it < 16) {
                        aA[it][h] = __ldcg((const uint2*)(g_hpk + ((size_t)row * 16 + it) * 8 + lq * 2));
                    } else {
                        aA[it][h] = __ldcg((const uint2*)(g_xpk + ((size_t)t * 512 + row) * 8 + lq * 2));
                    }
                }
            }

            float acc[4][4][4];
#pragma unroll
            for (int g = 0; g < 4; g++)
#pragma unroll
                for (int nj = 0; nj < 4; nj++)
#pragma unroll
                    for (int q = 0; q < 4; q++) acc[g][nj][q] = 0.0f;

#pragma unroll
            for (int it = 0; it < 17; ++it) {
                uint32_t AH[4] = { aA[it][0].x, aA[it][1].x, aA[it][0].y, aA[it][1].y };
#pragma unroll
                for (int g = 0; g < 4; g++) {
#pragma unroll
                    for (int jp = 0; jp < 2; jp++) {
                        uint4 h4 = *(const uint4*)&sWg[((((it * 4 + g) * 2 + jp) * 32 + lane)) * 4];
                        mma_f16(acc[g][2 * jp + 0], AH, h4.x, h4.y);
                        mma_f16(acc[g][2 * jp + 1], AH, h4.z, h4.w);
                    }
                }
            }

            // epilogue: + Zc(smem), LSTM cell (c in regs), write pair-packed hraw
#pragma unroll
            for (int h = 0; h < 2; h++) {
                int ml = wid * 16 + h * 8 + l4;
                int m = m0 + ml;
#pragma unroll
                for (int nj = 0; nj < 4; nj++) {
                    int jl = nj * 8 + 2 * lq;
                    float pre0[4], pre1[4];
#pragma unroll
                    for (int g = 0; g < 4; g++) {
                        float2 zc = *(const float2*)&sZc[ml * 128 + g * 32 + jl];
                        pre0[g] = acc[g][nj][2 * h + 0] + zc.x;
                        pre1[g] = acc[g][nj][2 * h + 1] + zc.y;
                    }
                    float cn0 = sigf(pre0[1]) * creg[h][nj][0] + sigf(pre0[0]) * tanh_f(pre0[2]);
                    float cn1 = sigf(pre1[1]) * creg[h][nj][1] + sigf(pre1[0]) * tanh_f(pre1[2]);
                    creg[h][nj][0] = cn0;
                    creg[h][nj][1] = cn1;
                    float hr0 = sigf(pre0[3]) * tanh_f(cn0);
                    float hr1 = sigf(pre1[3]) * tanh_f(cn1);
                    int q = 2 * lq + (nj & 1);
                    int kc = ct * 2 + (nj >> 1);
                    g_hrawpk[((size_t)m * 64 + kc) * 8 + q] = pack_h2(hr0, hr1);
                }
            }
        }
        grid_bar(++bar * NCTA);

        // ================= projection phase (4-way split-K, batched A) =================
        {
            int wm = wid >> 2;          // 0..1  (16 m-rows each)
            int kq = wid & 3;           // 0..3  (16 kc each)
            int mbase = mt2 * 32 + wm * 16;

            // batched A: all 32 LDG.64 issued up-front (MLP=32, one latency)
            uint2 aA[16][2];
#pragma unroll
            for (int kk = 0; kk < 16; kk++) {
                int kc = kq * 16 + kk;
#pragma unroll
                for (int h = 0; h < 2; h++) {
                    int row = mbase + h * 8 + l4;
                    aA[kk][h] = __ldcg((const uint2*)&g_hrawpk[((size_t)row * 64 + kc) * 8 + lq * 2]);
                }
            }

            float acc[4][4];
#pragma unroll
            for (int rs = 0; rs < 4; rs++)
#pragma unroll
                for (int q = 0; q < 4; q++) acc[rs][q] = 0.0f;

#pragma unroll
            for (int kk = 0; kk < 16; kk++) {
                int kc = kq * 16 + kk;
                uint32_t AH[4] = { aA[kk][0].x, aA[kk][1].x, aA[kk][0].y, aA[kk][1].y };
#pragma unroll
                for (int rs = 0; rs < 4; rs++) {
                    uint2 bh = *(const uint2*)&sWp[(rs * 64 + kc) * 64 + lane * 2];
                    mma_f16(acc[rs], AH, bh.x, bh.y);
                }
            }

            if (kq != 0) {
#pragma unroll
                for (int rs = 0; rs < 4; rs++) {
                    int slot = (((wm * 3 + (kq - 1)) * 4 + rs) * 32 + lane) * 4;
                    *(float4*)&sRed[slot] = make_float4(acc[rs][0], acc[rs][1], acc[rs][2], acc[rs][3]);
                }
            }
            __syncthreads();
            if (kq == 0) {
#pragma unroll
                for (int rs = 0; rs < 4; rs++) {
#pragma unroll
                    for (int p = 0; p < 3; p++) {
                        int slot = (((wm * 3 + p) * 4 + rs) * 32 + lane) * 4;
                        float4 o = *(const float4*)&sRed[slot];
                        acc[rs][0] += o.x;
                        acc[rs][1] += o.y;
                        acc[rs][2] += o.z;
                        acc[rs][3] += o.w;
                    }
                    int r = rt2 * 32 + rs * 8 + 2 * lq;
                    int kc_h = rt2 * 2 + (rs >> 1);
                    int q = 2 * lq + (rs & 1);
#pragma unroll
                    for (int h = 0; h < 2; h++) {
                        int m = mbase + h * 8 + l4;
                        float v0 = acc[rs][2 * h + 0];
                        float v1 = acc[rs][2 * h + 1];
                        *(float2*)&g_hs[((size_t)m * SS + t) * PP + r] = make_float2(v0, v1);
                        g_hpk[((size_t)m * 16 + kc_h) * 8 + q] = pack_h2(v0, v1);
                    }
                }
            }
        }
        grid_bar(++bar * NCTA);
    }
}

// ---------------- output heads: LN + command logits + coords (warp per row) ----------------
__global__ __launch_bounds__(256) void head_kernel(
    const float* __restrict__ ln_g, const float* __restrict__ ln_b,
    const float* __restrict__ W_oc, const float* __restrict__ b_oc,
    const float* __restrict__ W_ox, const float* __restrict__ b_ox,
    const float* __restrict__ scale_p, float* __restrict__ out)
{
    int gw = (blockIdx.x * 256 + threadIdx.x) >> 5;
    int lane = threadIdx.x & 31;
    if (gw >= BB * SS) return;

    const float* hrow = g_hs + (size_t)gw * PP;
    float v[8];
#pragma unroll
    for (int q = 0; q < 2; q++) {
        float4 f = *reinterpret_cast<const float4*>(hrow + lane * 8 + q * 4);
        v[q * 4 + 0] = f.x;
        v[q * 4 + 1] = f.y;
        v[q * 4 + 2] = f.z;
        v[q * 4 + 3] = f.w;
    }
    float s = 0.0f;
    float s2 = 0.0f;
#pragma unroll
    for (int e = 0; e < 8; e++) {
        s += v[e];
        s2 = fmaf(v[e], v[e], s2);
    }
#pragma unroll
    for (int o = 16; o > 0; o >>= 1) {
        s  += __shfl_xor_sync(0xFFFFFFFFu, s, o);
        s2 += __shfl_xor_sync(0xFFFFFFFFu, s2, o);
    }
    float mean = s * (1.0f / 256.0f);
    float var = s2 * (1.0f / 256.0f) - mean * mean;
    float rstd = rsqrtf(var + 1e-5f);

    float hn[8];
#pragma unroll
    for (int e = 0; e < 8; e++) {
        int c = lane * 8 + e;
        hn[e] = (v[e] - mean) * rstd * ln_g[c] + ln_b[c];
    }

    float lgs[10];
#pragma unroll
    for (int cc = 0; cc < 10; cc++) {
        float p = 0.0f;
#pragma unroll
        for (int e = 0; e < 8; e++)
            p = fmaf(hn[e], W_oc[cc * 256 + lane * 8 + e], p);
#pragma unroll
        for (int o = 16; o > 0; o >>= 1) p += __shfl_xor_sync(0xFFFFFFFFu, p, o);
        p += b_oc[cc];
        lgs[cc] = p;
        if (lane == cc) out[(size_t)gw * 10 + cc] = p;
    }

    float csc = *scale_p;
    float* outc = out + (size_t)BB * SS * 10;
#pragma unroll
    for (int q = 0; q < 6; q++) {
        float p = 0.0f;
#pragma unroll
        for (int e = 0; e < 8; e++)
            p = fmaf(hn[e], W_ox[q * 266 + lane * 8 + e], p);
#pragma unroll
        for (int o = 16; o > 0; o >>= 1) p += __shfl_xor_sync(0xFFFFFFFFu, p, o);
#pragma unroll
        for (int cc = 0; cc < 10; cc++)
            p = fmaf(lgs[cc], W_ox[q * 266 + 256 + cc], p);
        p += b_ox[q];
        float z = tanh_exact(p * csc);
        if (lane == q) outc[(size_t)gw * 6 + q] = z;
    }
}

// ---------------- launch ----------------
extern "C" void kernel_launch(void* const* d_in, const int* in_sizes, int n_in,
                              void* d_out, int out_size)
{
    const float* x      = (const float*)d_in[0];
    const float* ctx    = (const float*)d_in[1];
    const float* W_cmd  = (const float*)d_in[2];
    const float* b_cmd  = (const float*)d_in[3];
    const float* W_crd  = (const float*)d_in[4];
    const float* b_crd  = (const float*)d_in[5];
    const float* W_ih   = (const float*)d_in[6];
    const float* b_ih   = (const float*)d_in[7];
    const float* W_hh   = (const float*)d_in[8];
    const float* b_hh   = (const float*)d_in[9];
    const float* W_hr   = (const float*)d_in[10];
    const float* ln_g   = (const float*)d_in[11];
    const float* ln_b   = (const float*)d_in[12];
    const float* W_oc   = (const float*)d_in[13];
    const float* b_oc   = (const float*)d_in[14];
    const float* W_ox   = (const float*)d_in[15];
    const float* b_ox   = (const float*)d_in[16];
    const float* cscale = (const float*)d_in[17];
    float* out = (float*)d_out;

    static bool attr_set = false;
    if (!attr_set) {
        cudaFuncSetAttribute(lstm_persistent,
                             cudaFuncAttributeMaxDynamicSharedMemorySize,
                             SMEM_BYTES);
        attr_set = true;
    }

    prep_weff<<<G4, 128>>>(W_ih, b_ih, W_cmd, b_cmd, W_crd, b_crd, b_hh);
    prep_zc<<<dim3(G4 / 64, BB / 64), 256>>>(ctx, W_ih);
    pack_all<<<1424, 256>>>(W_hh, W_hr, x);

    lstm_persistent<<<NCTA, 256, SMEM_BYTES>>>();

    head_kernel<<<(BB * SS * 32 + 255) / 256, 256>>>(
        ln_g, ln_b, W_oc, b_oc, W_ox, b_ox, cscale, out);
}